// round 5
// baseline (speedup 1.0000x reference)
#include <cuda_runtime.h>
#include <math.h>

#define NN    1500
#define NE    48000
#define ET    (NE + NN)       // 49500
#define IND   128
#define OUTC  32
#define HEADS 4
#define HC    128
#define EDIM  16

#define NBLK  592
#define NTHR  256
#define NWRP  (NBLK * 8)

// ---- one contiguous zeroed scratch block (single memset, incl barrier) ----
#define OFF_CNT   0
#define OFF_EASUM 1500
#define OFF_S1    25500
#define OFF_S2    31500
#define OFF_AGG1  37500
#define OFF_AGG2  229500
#define OFF_BAR   421500          // 2 ints (count, sense)
#define ZTOTAL    421504
__device__ __align__(16) float g_z[ZTOTAL];

// non-zeroed scratch (separate layer-1 / layer-2 buffers: L1 non-coherence)
__device__ float g_weatt[EDIM * HEADS];
__device__ __align__(16) float g_h[NN * HC];
__device__ __align__(16) float g_as[NN * HEADS];
__device__ __align__(16) float g_ad[NN * HEADS];
__device__ __align__(16) float g_h2[NN * HC];
__device__ __align__(16) float g_as2[NN * HEADS];
__device__ __align__(16) float g_ad2[NN * HEADS];

#define FILL_BASE  (NE * 2 / 4)          // 24000 float4
#define FILL_TOTAL (NN * NN * 2 / 4)     // 1125000 float4

// ---- grid barrier: all NBLK blocks co-resident (enforced by launch_bounds) --
__device__ __forceinline__ void gbar(int phase) {
    __threadfence();                       // release: all threads' prior writes
    __syncthreads();
    if (threadIdx.x == 0) {
        int* cnt = (int*)(g_z + OFF_BAR);
        volatile int* sen = (volatile int*)(g_z + OFF_BAR + 1);
        if (atomicAdd(cnt, 1) == NBLK - 1) {
            atomicExch(cnt, 0);
            __threadfence();
            *sen = phase;
        } else {
            while (*sen < phase) { }
            __threadfence();
        }
    }
    __syncthreads();
}

// ---- edge pass body: alpha -> leaky -> exp -> atomic s / atomic agg --------
__device__ __forceinline__ void edge_pass(const int* __restrict__ edges,
                                          const float* __restrict__ ef,
                                          const float* __restrict__ hbuf,
                                          const float* __restrict__ asb,
                                          const float* __restrict__ adb,
                                          float* __restrict__ s_out,
                                          float* __restrict__ agg,
                                          bool has_extra, int bid, int warp, int lane) {
    int h = lane >> 3;
    for (int gw = bid * 8 + warp; gw < ET; gw += NWRP) {
        int src, dst;
        if (gw < NE) { src = edges[gw]; dst = edges[NE + gw]; }
        else         { src = dst = gw - NE; }
        float extra = 0.f;
        if (has_extra) {
            if (gw < NE) {
                #pragma unroll
                for (int d = 0; d < EDIM; d++)
                    extra = fmaf(ef[gw * EDIM + d], g_weatt[d * HEADS + h], extra);
            } else {
                float inv = 1.f / fmaxf(g_z[OFF_CNT + dst], 1.f);
                #pragma unroll
                for (int d = 0; d < EDIM; d++)
                    extra = fmaf(g_z[OFF_EASUM + dst * EDIM + d] * inv,
                                 g_weatt[d * HEADS + h], extra);
            }
        }
        float a = asb[src * HEADS + h] + adb[dst * HEADS + h] + extra;
        a = (a > 0.f) ? a : 0.2f * a;
        float e = expf(a);
        if ((lane & 7) == 0) atomicAdd(&s_out[dst * HEADS + h], e);
        float4 hv = reinterpret_cast<const float4*>(hbuf + src * HC)[lane];
        atomicAdd(&reinterpret_cast<float4*>(agg + dst * HC)[lane],
                  make_float4(e * hv.x, e * hv.y, e * hv.z, e * hv.w));
    }
}

__device__ __forceinline__ float x2_val(int node, int c, const float* __restrict__ b2) {
    const float* ag = &g_z[OFF_AGG2 + node * HC];
    float4 sv = *reinterpret_cast<const float4*>(&g_z[OFF_S2 + node * HEADS]);
    return 0.25f * (ag[c] / sv.x + ag[OUTC + c] / sv.y +
                    ag[2 * OUTC + c] / sv.z + ag[3 * OUTC + c] / sv.w) + b2[c];
}

// ================= the single persistent kernel ==============================
__global__ void __launch_bounds__(NTHR, 6) k_fused(
    const int* __restrict__ edges, const float* __restrict__ ef,
    const float* __restrict__ x, const float* __restrict__ W1,
    const float* __restrict__ as1, const float* __restrict__ ad1,
    const float* __restrict__ We, const float* __restrict__ att_e,
    const float* __restrict__ b1, const float* __restrict__ W2,
    const float* __restrict__ as2w, const float* __restrict__ ad2w,
    const float* __restrict__ b2,
    const float* __restrict__ fc1_w, const float* __restrict__ fc1_b,
    const float* __restrict__ fc2_w, const float* __restrict__ fc2_b,
    float* __restrict__ out) {
    __shared__ float sh[2176];
    int tid = threadIdx.x, bid = blockIdx.x;
    int lane = tid & 31, warp = tid >> 5;

    // ================= phase A: prep | proj1 | fill ==========================
    if (bid == 0 && tid < EDIM * HEADS) {
        int d = tid / HEADS, h = tid % HEADS;
        float acc = 0.f;
        #pragma unroll
        for (int c = 0; c < OUTC; c++)
            acc = fmaf(We[d * HC + h * OUTC + c], att_e[h * OUTC + c], acc);
        g_weatt[d * HEADS + h] = acc;
    }
    {   // prep: blocks 0..187
        int t = bid * NTHR + tid;
        if (t < NE) {
            int dst = edges[NE + t];
            const float4* efr = reinterpret_cast<const float4*>(ef + t * EDIM);
            float4* dp = reinterpret_cast<float4*>(&g_z[OFF_EASUM + dst * EDIM]);
            #pragma unroll
            for (int q = 0; q < 4; q++) atomicAdd(&dp[q], efr[q]);
            atomicAdd(&g_z[OFF_CNT + dst], 1.f);
        }
    }
    {   // proj1: 375 tiles of 4 rows, blocks 217..591
        int it = bid - 217;
        if (it >= 0 && it < 375) {
            int i0 = it * 4;
            for (int idx = tid; idx < 4 * IND; idx += NTHR)
                sh[idx] = x[i0 * IND + idx];
            __syncthreads();
            int j = tid & 127, half = tid >> 7;
            const float* xr = sh + (half * 2) * IND;
            float a0 = 0.f, a1 = 0.f;
            #pragma unroll 8
            for (int k = 0; k < IND; k++) {
                float w = W1[k * HC + j];
                a0 = fmaf(xr[k],       w, a0);
                a1 = fmaf(xr[IND + k], w, a1);
            }
            int h = j >> 5;
            float asw = as1[h * OUTC + lane], adw = ad1[h * OUTC + lane];
            float accs[2] = {a0, a1};
            #pragma unroll
            for (int r = 0; r < 2; r++) {
                int row = i0 + half * 2 + r;
                g_h[row * HC + j] = accs[r];
                float s = accs[r] * asw, d = accs[r] * adw;
                #pragma unroll
                for (int off = 16; off > 0; off >>= 1) {
                    s += __shfl_down_sync(0xffffffffu, s, off);
                    d += __shfl_down_sync(0xffffffffu, d, off);
                }
                if (lane == 0) {
                    g_as[row * HEADS + h] = s;
                    g_ad[row * HEADS + h] = d;
                }
            }
        }
    }
    {   // fill: all blocks grid-stride over rows >= NE
        float z0 = fc2_b[0], z1 = fc2_b[1];
        #pragma unroll
        for (int c = 0; c < 32; c++) {
            float hc = fmaxf(fc1_b[c], 0.f);
            z0 = fmaf(hc, fc2_w[c * 2 + 0], z0);
            z1 = fmaf(hc, fc2_w[c * 2 + 1], z1);
        }
        float mm = fmaxf(z0, z1);
        float e0 = expf(z0 - mm), e1 = expf(z1 - mm);
        float inv = 1.f / (e0 + e1);
        float4 v = make_float4(e0 * inv, e1 * inv, e0 * inv, e1 * inv);
        for (int idx = FILL_BASE + bid * NTHR + tid; idx < FILL_TOTAL; idx += NBLK * NTHR)
            reinterpret_cast<float4*>(out)[idx] = v;
    }

    gbar(1);

    // ================= phase B: edge pass layer 1 ============================
    edge_pass(edges, ef, g_h, g_as, g_ad, g_z + OFF_S1, g_z + OFF_AGG1,
              true, bid, warp, lane);

    gbar(2);

    // ================= phase C: proj2 (375 tiles of 4 rows) ==================
    if (bid < 375) {
        int i0 = bid * 4;
        if (tid < 128) {  // x1 on the fly from agg1/s1
            int row = i0 + (tid >> 5), c = tid & 31;
            const float* ag = &g_z[OFF_AGG1 + row * HC];
            float4 sv = *reinterpret_cast<const float4*>(&g_z[OFF_S1 + row * HEADS]);
            sh[tid] = 0.25f * (ag[c] / sv.x + ag[OUTC + c] / sv.y +
                               ag[2 * OUTC + c] / sv.z + ag[3 * OUTC + c] / sv.w) + b1[c];
        }
        __syncthreads();
        int j = tid & 127, half = tid >> 7;
        const float* xr = sh + (half * 2) * OUTC;
        float a0 = 0.f, a1 = 0.f;
        #pragma unroll
        for (int k = 0; k < OUTC; k++) {
            float w = W2[k * HC + j];
            a0 = fmaf(xr[k],        w, a0);
            a1 = fmaf(xr[OUTC + k], w, a1);
        }
        int h = j >> 5;
        float asw = as2w[h * OUTC + lane], adw = ad2w[h * OUTC + lane];
        float accs[2] = {a0, a1};
        #pragma unroll
        for (int r = 0; r < 2; r++) {
            int row = i0 + half * 2 + r;
            g_h2[row * HC + j] = accs[r];
            float s = accs[r] * asw, d = accs[r] * adw;
            #pragma unroll
            for (int off = 16; off > 0; off >>= 1) {
                s += __shfl_down_sync(0xffffffffu, s, off);
                d += __shfl_down_sync(0xffffffffu, d, off);
            }
            if (lane == 0) {
                g_as2[row * HEADS + h] = s;
                g_ad2[row * HEADS + h] = d;
            }
        }
    }

    gbar(3);

    // ================= phase D: edge pass layer 2 ============================
    edge_pass(edges, ef, g_h2, g_as2, g_ad2, g_z + OFF_S2, g_z + OFF_AGG2,
              false, bid, warp, lane);

    gbar(4);

    // ================= phase E: classifier ===================================
    for (int i = tid; i < 2048; i += NTHR) sh[i] = fc1_w[i];
    if (tid < 32) sh[2048 + tid] = fc1_b[tid];
    if (tid < 64) sh[2080 + tid] = fc2_w[tid];
    if (tid < 2)  sh[2144 + tid] = fc2_b[tid];
    __syncthreads();

    for (int e = bid * 8 + warp; e < NE; e += NWRP) {
        int s0 = edges[e], d0 = edges[NE + e];
        float plo = x2_val(s0, lane, b2);
        float phi = x2_val(d0, lane, b2);
        float acc = sh[2048 + lane];
        #pragma unroll
        for (int k = 0; k < 32; k++)
            acc = fmaf(__shfl_sync(0xffffffffu, plo, k), sh[k * 32 + lane], acc);
        #pragma unroll
        for (int k = 0; k < 32; k++)
            acc = fmaf(__shfl_sync(0xffffffffu, phi, k), sh[(32 + k) * 32 + lane], acc);
        acc = fmaxf(acc, 0.f);
        float z0 = acc * sh[2080 + lane * 2 + 0];
        float z1 = acc * sh[2080 + lane * 2 + 1];
        #pragma unroll
        for (int off = 16; off > 0; off >>= 1) {
            z0 += __shfl_down_sync(0xffffffffu, z0, off);
            z1 += __shfl_down_sync(0xffffffffu, z1, off);
        }
        if (lane == 0) {
            z0 += sh[2144]; z1 += sh[2145];
            float mm = fmaxf(z0, z1);
            float e0 = expf(z0 - mm), e1 = expf(z1 - mm);
            float inv = 1.f / (e0 + e1);
            out[2 * e]     = e0 * inv;
            out[2 * e + 1] = e1 * inv;
        }
    }
}

// ---- launch ------------------------------------------------------------------
extern "C" void kernel_launch(void* const* d_in, const int* in_sizes, int n_in,
                              void* d_out, int out_size) {
    const float* x        = (const float*)d_in[0];
    const int*   edges    = (const int*)d_in[1];
    const float* ef       = (const float*)d_in[2];
    const float* W1       = (const float*)d_in[3];
    const float* att_src1 = (const float*)d_in[4];
    const float* att_dst1 = (const float*)d_in[5];
    const float* We       = (const float*)d_in[6];
    const float* att_e    = (const float*)d_in[7];
    const float* b1       = (const float*)d_in[8];
    const float* W2       = (const float*)d_in[9];
    const float* att_src2 = (const float*)d_in[10];
    const float* att_dst2 = (const float*)d_in[11];
    const float* b2       = (const float*)d_in[12];
    const float* fc1_w    = (const float*)d_in[13];
    const float* fc1_b    = (const float*)d_in[14];
    const float* fc2_w    = (const float*)d_in[15];
    const float* fc2_b    = (const float*)d_in[16];
    float* out = (float*)d_out;

    float* zbase; cudaGetSymbolAddress((void**)&zbase, g_z);
    cudaMemsetAsync(zbase, 0, ZTOTAL * sizeof(float));

    k_fused<<<NBLK, NTHR>>>(edges, ef, x, W1, att_src1, att_dst1, We, att_e,
                            b1, W2, att_src2, att_dst2, b2,
                            fc1_w, fc1_b, fc2_w, fc2_b, out);
}

// round 6
// speedup vs baseline: 1.1520x; 1.1520x over previous
#include <cuda_runtime.h>
#include <math.h>

#define NN    1500
#define NE    48000
#define ET    (NE + NN)       // 49500
#define IND   128
#define OUTC  32
#define HEADS 4
#define HC    128
#define EDIM  16

#define NBLK  592
#define NTHR  256
#define NWRP  (NBLK * 8)

// ---- one contiguous zeroed scratch block (single memset, incl barrier) ----
#define OFF_CNT   0
#define OFF_EASUM 1500
#define OFF_S1    25500
#define OFF_S2    31500
#define OFF_AGG1  37500
#define OFF_AGG2  229500
#define OFF_BAR   421500          // 2 ints (count, sense)
#define ZTOTAL    421504
__device__ __align__(16) float g_z[ZTOTAL];

// non-zeroed scratch (separate layer-1 / layer-2 buffers)
__device__ float g_weatt[EDIM * HEADS];
__device__ __align__(16) float g_h[NN * HC];
__device__ __align__(16) float g_as[NN * HEADS];
__device__ __align__(16) float g_ad[NN * HEADS];
__device__ __align__(16) float g_h2[NN * HC];
__device__ __align__(16) float g_as2[NN * HEADS];
__device__ __align__(16) float g_ad2[NN * HEADS];

#define FILL_BASE  (NE * 2 / 4)          // 24000 float4
#define FILL_TOTAL (NN * NN * 2 / 4)     // 1125000 float4

// ---- grid barrier WITHOUT membar.gl (no CCTL.IVALL L1 flush) ---------------
// release/acquire on the barrier words only; all inter-phase buffers are
// first-read-after-write so no L1 invalidation is needed.
__device__ __forceinline__ void gbar(int phase) {
    __syncthreads();
    if (threadIdx.x == 0) {
        int* cnt = (int*)(g_z + OFF_BAR);
        int* sen = (int*)(g_z + OFF_BAR + 1);
        int prev;
        asm volatile("atom.acq_rel.gpu.add.s32 %0, [%1], 1;"
                     : "=r"(prev) : "l"(cnt) : "memory");
        if (prev == NBLK - 1) {
            *cnt = 0;  // ordered before sense by the release below
            asm volatile("st.release.gpu.s32 [%0], %1;"
                         :: "l"(sen), "r"(phase) : "memory");
        } else {
            int v;
            do {
                asm volatile("ld.acquire.gpu.s32 %0, [%1];"
                             : "=r"(v) : "l"(sen) : "memory");
            } while (v < phase);
        }
    }
    __syncthreads();
}

// ---- edge pass body ---------------------------------------------------------
__device__ __forceinline__ void edge_pass(const int* __restrict__ edges,
                                          const float* __restrict__ ef,
                                          const float* __restrict__ hbuf,
                                          const float* __restrict__ asb,
                                          const float* __restrict__ adb,
                                          float* __restrict__ s_out,
                                          float* __restrict__ agg,
                                          bool has_extra, int bid, int warp, int lane) {
    int h = lane >> 3;
    for (int gw = bid * 8 + warp; gw < ET; gw += NWRP) {
        int src, dst;
        if (gw < NE) { src = edges[gw]; dst = edges[NE + gw]; }
        else         { src = dst = gw - NE; }
        float extra = 0.f;
        if (has_extra) {
            if (gw < NE) {
                #pragma unroll
                for (int d = 0; d < EDIM; d++)
                    extra = fmaf(ef[gw * EDIM + d], g_weatt[d * HEADS + h], extra);
            } else {
                float inv = __fdividef(1.f, fmaxf(g_z[OFF_CNT + dst], 1.f));
                #pragma unroll
                for (int d = 0; d < EDIM; d++)
                    extra = fmaf(g_z[OFF_EASUM + dst * EDIM + d] * inv,
                                 g_weatt[d * HEADS + h], extra);
            }
        }
        float a = asb[src * HEADS + h] + adb[dst * HEADS + h] + extra;
        a = (a > 0.f) ? a : 0.2f * a;
        float e = __expf(a);
        if ((lane & 7) == 0) atomicAdd(&s_out[dst * HEADS + h], e);
        float4 hv = reinterpret_cast<const float4*>(hbuf + src * HC)[lane];
        atomicAdd(&reinterpret_cast<float4*>(agg + dst * HC)[lane],
                  make_float4(e * hv.x, e * hv.y, e * hv.z, e * hv.w));
    }
}

__device__ __forceinline__ float x2_val(int node, int c, const float* __restrict__ b2) {
    const float* ag = &g_z[OFF_AGG2 + node * HC];
    float4 sv = *reinterpret_cast<const float4*>(&g_z[OFF_S2 + node * HEADS]);
    return 0.25f * (__fdividef(ag[c],            sv.x) +
                    __fdividef(ag[OUTC + c],     sv.y) +
                    __fdividef(ag[2 * OUTC + c], sv.z) +
                    __fdividef(ag[3 * OUTC + c], sv.w)) + b2[c];
}

// smem layout: [0..511] proj staging; [512..2559] fc1_w; [2560..2591] fc1_b;
//              [2592..2655] fc2_w; [2656..2657] fc2_b
#define SH_W1 512
#define SH_B1 2560
#define SH_W2 2592
#define SH_B2 2656

// ================= the single persistent kernel ==============================
__global__ void __launch_bounds__(NTHR, 4) k_fused(
    const int* __restrict__ edges, const float* __restrict__ ef,
    const float* __restrict__ x, const float* __restrict__ W1,
    const float* __restrict__ as1, const float* __restrict__ ad1,
    const float* __restrict__ We, const float* __restrict__ att_e,
    const float* __restrict__ b1, const float* __restrict__ W2,
    const float* __restrict__ as2w, const float* __restrict__ ad2w,
    const float* __restrict__ b2,
    const float* __restrict__ fc1_w, const float* __restrict__ fc1_b,
    const float* __restrict__ fc2_w, const float* __restrict__ fc2_b,
    float* __restrict__ out) {
    __shared__ float sh[2688];
    int tid = threadIdx.x, bid = blockIdx.x;
    int lane = tid & 31, warp = tid >> 5;

    // ================= phase A: prep | proj1 | fill ==========================
    if (bid == 0 && tid < EDIM * HEADS) {
        int d = tid / HEADS, h = tid % HEADS;
        float acc = 0.f;
        #pragma unroll
        for (int c = 0; c < OUTC; c++)
            acc = fmaf(We[d * HC + h * OUTC + c], att_e[h * OUTC + c], acc);
        g_weatt[d * HEADS + h] = acc;
    }
    {   // prep: blocks 0..187
        int t = bid * NTHR + tid;
        if (t < NE) {
            int dst = edges[NE + t];
            const float4* efr = reinterpret_cast<const float4*>(ef + t * EDIM);
            float4* dp = reinterpret_cast<float4*>(&g_z[OFF_EASUM + dst * EDIM]);
            #pragma unroll
            for (int q = 0; q < 4; q++) atomicAdd(&dp[q], efr[q]);
            atomicAdd(&g_z[OFF_CNT + dst], 1.f);
        }
    }
    if (bid >= 217) {   // proj1: 375 tiles of 4 rows, blocks 217..591
        int i0 = (bid - 217) * 4;
        for (int idx = tid; idx < 4 * IND; idx += NTHR)
            sh[idx] = x[i0 * IND + idx];
        __syncthreads();
        int j = tid & 127, half = tid >> 7;
        const float* xr = sh + (half * 2) * IND;
        float a0 = 0.f, a1 = 0.f;
        #pragma unroll 8
        for (int k = 0; k < IND; k++) {
            float w = W1[k * HC + j];
            a0 = fmaf(xr[k],       w, a0);
            a1 = fmaf(xr[IND + k], w, a1);
        }
        int h = j >> 5;
        float asw = as1[h * OUTC + lane], adw = ad1[h * OUTC + lane];
        float accs[2] = {a0, a1};
        #pragma unroll
        for (int r = 0; r < 2; r++) {
            int row = i0 + half * 2 + r;
            g_h[row * HC + j] = accs[r];
            float s = accs[r] * asw, d = accs[r] * adw;
            #pragma unroll
            for (int off = 16; off > 0; off >>= 1) {
                s += __shfl_down_sync(0xffffffffu, s, off);
                d += __shfl_down_sync(0xffffffffu, d, off);
            }
            if (lane == 0) {
                g_as[row * HEADS + h] = s;
                g_ad[row * HEADS + h] = d;
            }
        }
    } else {   // fill: blocks 0..216 grid-stride over constant rows >= NE
        float z0 = fc2_b[0], z1 = fc2_b[1];
        #pragma unroll
        for (int c = 0; c < 32; c++) {
            float hc = fmaxf(fc1_b[c], 0.f);
            z0 = fmaf(hc, fc2_w[c * 2 + 0], z0);
            z1 = fmaf(hc, fc2_w[c * 2 + 1], z1);
        }
        float mm = fmaxf(z0, z1);
        float e0 = __expf(z0 - mm), e1 = __expf(z1 - mm);
        float inv = __fdividef(1.f, e0 + e1);
        float4 v = make_float4(e0 * inv, e1 * inv, e0 * inv, e1 * inv);
        for (int idx = FILL_BASE + bid * NTHR + tid; idx < FILL_TOTAL; idx += 217 * NTHR)
            reinterpret_cast<float4*>(out)[idx] = v;
    }

    gbar(1);

    // ================= phase B: edge pass layer 1 ============================
    edge_pass(edges, ef, g_h, g_as, g_ad, g_z + OFF_S1, g_z + OFF_AGG1,
              true, bid, warp, lane);

    gbar(2);

    // ================= phase C: proj2 (375 tiles of 4 rows) ==================
    if (bid < 375) {
        int i0 = bid * 4;
        if (tid < 128) {  // x1 on the fly from agg1/s1
            int row = i0 + (tid >> 5), c = tid & 31;
            const float* ag = &g_z[OFF_AGG1 + row * HC];
            float4 sv = *reinterpret_cast<const float4*>(&g_z[OFF_S1 + row * HEADS]);
            sh[tid] = 0.25f * (__fdividef(ag[c],            sv.x) +
                               __fdividef(ag[OUTC + c],     sv.y) +
                               __fdividef(ag[2 * OUTC + c], sv.z) +
                               __fdividef(ag[3 * OUTC + c], sv.w)) + b1[c];
        }
        __syncthreads();
        int j = tid & 127, half = tid >> 7;
        const float* xr = sh + (half * 2) * OUTC;
        float a0 = 0.f, a1 = 0.f;
        #pragma unroll
        for (int k = 0; k < OUTC; k++) {
            float w = W2[k * HC + j];
            a0 = fmaf(xr[k],        w, a0);
            a1 = fmaf(xr[OUTC + k], w, a1);
        }
        int h = j >> 5;
        float asw = as2w[h * OUTC + lane], adw = ad2w[h * OUTC + lane];
        float accs[2] = {a0, a1};
        #pragma unroll
        for (int r = 0; r < 2; r++) {
            int row = i0 + half * 2 + r;
            g_h2[row * HC + j] = accs[r];
            float s = accs[r] * asw, d = accs[r] * adw;
            #pragma unroll
            for (int off = 16; off > 0; off >>= 1) {
                s += __shfl_down_sync(0xffffffffu, s, off);
                d += __shfl_down_sync(0xffffffffu, d, off);
            }
            if (lane == 0) {
                g_as2[row * HEADS + h] = s;
                g_ad2[row * HEADS + h] = d;
            }
        }
        __syncthreads();
    }

    // preload classifier weights NOW (independent of phase D; hides L2 latency)
    for (int i = tid; i < 2048; i += NTHR) sh[SH_W1 + i] = fc1_w[i];
    if (tid < 32) sh[SH_B1 + tid] = fc1_b[tid];
    if (tid < 64) sh[SH_W2 + tid] = fc2_w[tid];
    if (tid < 2)  sh[SH_B2 + tid] = fc2_b[tid];

    gbar(3);

    // ================= phase D: edge pass layer 2 ============================
    edge_pass(edges, ef, g_h2, g_as2, g_ad2, g_z + OFF_S2, g_z + OFF_AGG2,
              false, bid, warp, lane);

    gbar(4);

    // ================= phase E: classifier ===================================
    for (int e = bid * 8 + warp; e < NE; e += NWRP) {
        int s0 = edges[e], d0 = edges[NE + e];
        float plo = x2_val(s0, lane, b2);
        float phi = x2_val(d0, lane, b2);
        float acc = sh[SH_B1 + lane];
        #pragma unroll
        for (int k = 0; k < 32; k++)
            acc = fmaf(__shfl_sync(0xffffffffu, plo, k), sh[SH_W1 + k * 32 + lane], acc);
        #pragma unroll
        for (int k = 0; k < 32; k++)
            acc = fmaf(__shfl_sync(0xffffffffu, phi, k), sh[SH_W1 + (32 + k) * 32 + lane], acc);
        acc = fmaxf(acc, 0.f);
        float z0 = acc * sh[SH_W2 + lane * 2 + 0];
        float z1 = acc * sh[SH_W2 + lane * 2 + 1];
        #pragma unroll
        for (int off = 16; off > 0; off >>= 1) {
            z0 += __shfl_down_sync(0xffffffffu, z0, off);
            z1 += __shfl_down_sync(0xffffffffu, z1, off);
        }
        if (lane == 0) {
            z0 += sh[SH_B2]; z1 += sh[SH_B2 + 1];
            float mm = fmaxf(z0, z1);
            float e0 = __expf(z0 - mm), e1 = __expf(z1 - mm);
            float inv = __fdividef(1.f, e0 + e1);
            out[2 * e]     = e0 * inv;
            out[2 * e + 1] = e1 * inv;
        }
    }
}

// ---- launch ------------------------------------------------------------------
extern "C" void kernel_launch(void* const* d_in, const int* in_sizes, int n_in,
                              void* d_out, int out_size) {
    const float* x        = (const float*)d_in[0];
    const int*   edges    = (const int*)d_in[1];
    const float* ef       = (const float*)d_in[2];
    const float* W1       = (const float*)d_in[3];
    const float* att_src1 = (const float*)d_in[4];
    const float* att_dst1 = (const float*)d_in[5];
    const float* We       = (const float*)d_in[6];
    const float* att_e    = (const float*)d_in[7];
    const float* b1       = (const float*)d_in[8];
    const float* W2       = (const float*)d_in[9];
    const float* att_src2 = (const float*)d_in[10];
    const float* att_dst2 = (const float*)d_in[11];
    const float* b2       = (const float*)d_in[12];
    const float* fc1_w    = (const float*)d_in[13];
    const float* fc1_b    = (const float*)d_in[14];
    const float* fc2_w    = (const float*)d_in[15];
    const float* fc2_b    = (const float*)d_in[16];
    float* out = (float*)d_out;

    float* zbase; cudaGetSymbolAddress((void**)&zbase, g_z);
    cudaMemsetAsync(zbase, 0, ZTOTAL * sizeof(float));

    k_fused<<<NBLK, NTHR>>>(edges, ef, x, W1, att_src1, att_dst1, We, att_e,
                            b1, W2, att_src2, att_dst2, b2,
                            fc1_w, fc1_b, fc2_w, fc2_b, out);
}